// round 2
// baseline (speedup 1.0000x reference)
#include <cuda_runtime.h>
#include <cuda_bf16.h>

// binnings: out[b,g,h,w] = sum_n x[b, IDX[g,n], h, w] * groupn[g,n]
//   x: (8, 64, 512, 512) fp32, groupn: (16, 4) fp32, out: (8, 16, 512, 512)
//   IDX[g,n] = (g/4)*16 + n*4 + (g%4)
//
// Pure HBM-bound. 671 MB total traffic (512 read + 128 write, minimal).
// R2: 2 float4s per thread (8 in-flight LDG.128 -> better MLP),
//     streaming cache hints (__ldcs/__stcs) since data has zero reuse.

static constexpr int B = 8;
static constexpr int C = 64;
static constexpr int G = 16;
static constexpr int HW = 512 * 512;
static constexpr int HW4 = HW / 4;            // 65536 float4s per plane
static constexpr int V = 2;                   // float4s per thread
static constexpr int TPB = 256;

__global__ __launch_bounds__(TPB)
void binnings_kernel(const float4* __restrict__ x,
                     const float* __restrict__ groupn,
                     float4* __restrict__ out)
{
    const int g = blockIdx.y;
    const int b = blockIdx.z;
    // each block covers V*TPB consecutive float4s of the plane
    const int p0 = blockIdx.x * (TPB * V) + threadIdx.x;

    const int ch_base = (g >> 2) * 16 + (g & 3);

    const float w0 = __ldg(&groupn[g * 4 + 0]);
    const float w1 = __ldg(&groupn[g * 4 + 1]);
    const float w2 = __ldg(&groupn[g * 4 + 2]);
    const float w3 = __ldg(&groupn[g * 4 + 3]);

    const long long in_base  = (long long)(b * C + ch_base) * HW4;
    const long long out_base = (long long)(b * G + g) * HW4;

    float4 a0[V], a1[V], a2[V], a3[V];

    #pragma unroll
    for (int v = 0; v < V; v++) {
        const long long p = in_base + p0 + v * TPB;
        a0[v] = __ldcs(&x[p + 0LL * 4 * HW4]);
        a1[v] = __ldcs(&x[p + 1LL * 4 * HW4]);
        a2[v] = __ldcs(&x[p + 2LL * 4 * HW4]);
        a3[v] = __ldcs(&x[p + 3LL * 4 * HW4]);
    }

    #pragma unroll
    for (int v = 0; v < V; v++) {
        float4 r;
        r.x = fmaf(a0[v].x, w0, fmaf(a1[v].x, w1, fmaf(a2[v].x, w2, a3[v].x * w3)));
        r.y = fmaf(a0[v].y, w0, fmaf(a1[v].y, w1, fmaf(a2[v].y, w2, a3[v].y * w3)));
        r.z = fmaf(a0[v].z, w0, fmaf(a1[v].z, w1, fmaf(a2[v].z, w2, a3[v].z * w3)));
        r.w = fmaf(a0[v].w, w0, fmaf(a1[v].w, w1, fmaf(a2[v].w, w2, a3[v].w * w3)));
        __stcs(&out[out_base + p0 + v * TPB], r);
    }
}

extern "C" void kernel_launch(void* const* d_in, const int* in_sizes, int n_in,
                              void* d_out, int out_size)
{
    const float4* x      = (const float4*)d_in[0];
    const float*  groupn = (const float*)d_in[1];
    float4*       out    = (float4*)d_out;

    dim3 block(TPB);
    dim3 grid(HW4 / (TPB * V), G, B);   // 128 x 16 x 8 = 16384 blocks
    binnings_kernel<<<grid, block>>>(x, groupn, out);
}